// round 14
// baseline (speedup 1.0000x reference)
#include <cuda_runtime.h>
#include <cuda_fp16.h>
#include <cstdint>

// ---------------------------------------------------------------------------
// B=32, CIN=256, COUT=256, 64x64 -> 32x32, 3x3 stride2 pad1 conv. Crop mask
// all-True => plain conv. Single-pass fp16 m16n8k16 implicit GEMM.
// Round 14: PERSISTENT kernel (296 CTAs, 2/SM) + dynamic tile work-stealing
// over 512 tiles -> removes CTA-wave imbalance. KC=96, 2-stage pipeline.
// ---------------------------------------------------------------------------

#define B_    32
#define CIN_  256
#define COUT_ 256
#define H_    64
#define W_    64
#define HW_   4096
#define NPIX_ 1024
#define KTOT  2304

#define BM 128
#define BN 128
#define KC 96
#define NIT 24                 // 2304 / 96
#define NTILES 512             // 2 m-tiles * 256 n-tiles
#define NCTA  296              // 148 SMs * 2

#define ROW_B    208           // 192B payload + 16B pad
#define A_OFF    0
#define B_OFF2   (128 * ROW_B)             // 26624
#define STAGE_B  (B_OFF2 + 128 * ROW_B)    // 53248
#define TILES_OFF 1024
#define NSTAGE   2
#define SMEM_TOTAL (TILES_OFF + NSTAGE * STAGE_B)   // 107520 (x2 CTAs = 215040)

__device__ __align__(128) __half g_A[COUT_ * KTOT];             // [cout][p*256+cin]
__device__ __align__(128) __half g_X[(size_t)B_ * HW_ * CIN_];  // [b][s][cin]
__device__ unsigned int g_ctr;

// ---------------------------------------------------------------------------
__device__ __forceinline__ uint32_t smem_u32(const void* p) {
    uint32_t a;
    asm("{ .reg .u64 t; cvta.to.shared.u64 t, %1; cvt.u32.u64 %0, t; }" : "=r"(a) : "l"(p));
    return a;
}
__device__ __forceinline__ void bulk_g2s(uint32_t dst, const void* src, uint32_t bytes,
                                         uint32_t mbar) {
    asm volatile(
        "cp.async.bulk.shared::cluster.global.mbarrier::complete_tx::bytes "
        "[%0], [%1], %2, [%3];"
        :: "r"(dst), "l"(src), "r"(bytes), "r"(mbar) : "memory");
}
__device__ __forceinline__ void mbar_init(uint32_t a, uint32_t cnt) {
    asm volatile("mbarrier.init.shared.b64 [%0], %1;" :: "r"(a), "r"(cnt) : "memory");
}
__device__ __forceinline__ void mbar_expect_tx(uint32_t a, uint32_t tx) {
    asm volatile("mbarrier.arrive.expect_tx.shared.b64 _, [%0], %1;"
                 :: "r"(a), "r"(tx) : "memory");
}
__device__ __forceinline__ void mbar_wait(uint32_t a, uint32_t parity) {
    asm volatile(
        "{\n\t.reg .pred P1;\n\t"
        "W_%=:\n\t"
        "mbarrier.try_wait.parity.acquire.cta.shared::cta.b64 P1, [%0], %1, 0x989680;\n\t"
        "@!P1 bra W_%=;\n\t}"
        :: "r"(a), "r"(parity) : "memory");
}
__device__ __forceinline__ void mma_fp16(float* d, const uint32_t* a, uint32_t b0, uint32_t b1) {
    asm volatile(
        "mma.sync.aligned.m16n8k16.row.col.f32.f16.f16.f32 "
        "{%0,%1,%2,%3}, {%4,%5,%6,%7}, {%8,%9}, {%0,%1,%2,%3};"
        : "+f"(d[0]), "+f"(d[1]), "+f"(d[2]), "+f"(d[3])
        : "r"(a[0]), "r"(a[1]), "r"(a[2]), "r"(a[3]), "r"(b0), "r"(b1));
}
__device__ __forceinline__ void ldm4(uint32_t* r, uint32_t addr) {
    asm volatile("ldmatrix.sync.aligned.m8n8.x4.shared.b16 {%0,%1,%2,%3}, [%4];"
                 : "=r"(r[0]), "=r"(r[1]), "=r"(r[2]), "=r"(r[3]) : "r"(addr));
}

// ---------------------------------------------------------------------------
// Fused prologue: blocks [0, 2304) -> weight convert; rest -> x convert.
// Block 0 also zeroes the persistent-scheduler counter.
// ---------------------------------------------------------------------------
__global__ void transform_kernel(const float* __restrict__ x, const float* __restrict__ w) {
    __shared__ float tile[32][33];   // tile[c_local][s_local]
    const int tid = threadIdx.x;
    if (blockIdx.x == 0 && tid == 0) g_ctr = 0u;
    if (blockIdx.x < 2304) {
        int idx = blockIdx.x * 256 + tid;   // linear over [cout][p][cin]
        int cin = idx & 255;
        int p = (idx >> 8) % 9;
        int cout = idx / KTOT;
        g_A[idx] = __float2half_rn(w[cout * KTOT + cin * 9 + p]);
        return;
    }
    const int t = blockIdx.x - 2304;
    const int s0 = (t & 127) * 32;
    const int c0 = ((t >> 7) & 7) * 32;
    const int b = t >> 10;
    const int tx = tid & 31, ty = tid >> 5;         // 32 x 8
    const float* xb = x + ((size_t)b * CIN_ + c0) * HW_ + s0;
#pragma unroll
    for (int k = 0; k < 4; ++k)
        tile[ty + 8 * k][tx] = xb[(size_t)(ty + 8 * k) * HW_ + tx];   // tile[c][s]
    __syncthreads();
    const int c2 = (tid & 15) * 2;
#pragma unroll
    for (int k = 0; k < 2; ++k) {
        const int s = (tid >> 4) + 16 * k;
        __half2 v = __floats2half2_rn(tile[c2][s], tile[c2 + 1][s]);
        size_t o = ((size_t)b * HW_ + s0 + s) * CIN_ + c0 + c2;
        *(__half2*)(g_X + o) = v;
    }
}

// ---------------------------------------------------------------------------
// Main persistent fp16 implicit-GEMM. grid 296, 256 threads, 2 CTAs/SM.
// ---------------------------------------------------------------------------
__global__ void __launch_bounds__(256, 2) conv_fp16_kernel(float* __restrict__ out) {
    extern __shared__ char smem[];
    const uint32_t sb = smem_u32(smem);
    const int tid = threadIdx.x;
    const int lane = tid & 31, warp = tid >> 5;

    if (tid < NSTAGE) mbar_init(sb + tid * 16, 1);
    asm volatile("fence.proxy.async.shared::cta;" ::: "memory");
    __syncthreads();

    const int mw = (warp >> 1) * 32;      // 0,32,64,96
    const int nw = (warp & 1) * 64;       // 0,64
    uint32_t aOff[2], bOff[4];
#pragma unroll
    for (int mi = 0; mi < 2; ++mi)
        aOff[mi] = (uint32_t)(A_OFF + (mw + mi * 16 + (lane & 15)) * ROW_B
                   + (lane >> 4) * 16);
#pragma unroll
    for (int nj = 0; nj < 4; ++nj)
        bOff[nj] = (uint32_t)(B_OFF2
                 + (nw + nj * 16 + (lane & 7) + (lane >> 4) * 8) * ROW_B
                 + ((lane >> 3) & 1) * 16);
    const int lg = lane >> 2;
    const int lc = lane & 3;

    int ph[NSTAGE] = {0, 0};              // persistent across tiles (even flips/tile)

    volatile unsigned int* tslot = (volatile unsigned int*)(smem + 32);

#pragma unroll 1
    for (;;) {
        // ---- fetch next tile ----
        if (tid == 0) *tslot = atomicAdd(&g_ctr, 1u);
        __syncthreads();
        const unsigned int t = *tslot;
        if (t >= NTILES) break;
        const int m0 = (int)(t & 1) * BM;
        const int nt = (int)(t >> 1);
        const int b = nt >> 3;                        // 8 n-tiles per batch
        const int pix0 = (nt & 7) * BN;

        const int pixL = pix0 + (tid & 127);
        const int ohL = pixL >> 5, owL = pixL & 31;
        const __half* gX0 = g_X + (size_t)b * HW_ * CIN_;

        auto inv_rows = [&](int p) -> int {
            const int kh = p / 3, kw = p - (p / 3) * 3;
            int inv = (kw == 0 ? 4 : 0) + ((kh == 0 && pix0 == 0) ? 32 : 0);
            if (kw == 0 && kh == 0 && pix0 == 0) inv -= 1;
            return inv;
        };

        auto load_stage = [&](int buf, int it) {
            const int k0 = it * KC;
            const int p1 = k0 >> 8;
            const int o1 = k0 & 255;
            const int len1 = (256 - o1 < KC) ? (256 - o1) : KC;
            const int len2 = KC - len1;
            const uint32_t st = sb + TILES_OFF + buf * STAGE_B;
            const uint32_t mb = sb + buf * 16;
            if (tid == 0) {
                uint32_t txB = 2u * (uint32_t)len1 * (uint32_t)(128 - inv_rows(p1));
                if (len2) txB += 2u * (uint32_t)len2 * (uint32_t)(128 - inv_rows(p1 + 1));
                mbar_expect_tx(mb, 128u * 192u + txB);
            }
            const int r = tid & 127;
            if (tid < 128) {
                bulk_g2s(st + A_OFF + r * ROW_B,
                         g_A + (size_t)(m0 + r) * KTOT + k0, KC * 2, mb);
            } else {
                const uint32_t dst = st + B_OFF2 + r * ROW_B;
                {
                    const int kh = p1 / 3, kw = p1 - (p1 / 3) * 3;
                    const int ih = ohL * 2 - 1 + kh;
                    const int iw = owL * 2 - 1 + kw;
                    if (((unsigned)ih < (unsigned)H_) && ((unsigned)iw < (unsigned)W_)) {
                        bulk_g2s(dst, gX0 + (size_t)(ih * W_ + iw) * CIN_ + o1, len1 * 2, mb);
                    } else {
                        for (int j = 0; j < len1 * 2; j += 16)
                            asm volatile("st.shared.v4.b32 [%0], {%1, %1, %1, %1};"
                                         :: "r"(dst + j), "r"(0u) : "memory");
                    }
                }
                if (len2) {
                    const int p2 = p1 + 1;
                    const int kh = p2 / 3, kw = p2 - (p2 / 3) * 3;
                    const int ih = ohL * 2 - 1 + kh;
                    const int iw = owL * 2 - 1 + kw;
                    const uint32_t d2 = dst + len1 * 2;
                    if (((unsigned)ih < (unsigned)H_) && ((unsigned)iw < (unsigned)W_)) {
                        bulk_g2s(d2, gX0 + (size_t)(ih * W_ + iw) * CIN_, len2 * 2, mb);
                    } else {
                        for (int j = 0; j < len2 * 2; j += 16)
                            asm volatile("st.shared.v4.b32 [%0], {%1, %1, %1, %1};"
                                         :: "r"(d2 + j), "r"(0u) : "memory");
                    }
                }
            }
        };

        float acc[2][8][4];
#pragma unroll
        for (int mi = 0; mi < 2; ++mi)
#pragma unroll
            for (int ni = 0; ni < 8; ++ni)
#pragma unroll
                for (int j = 0; j < 4; ++j) acc[mi][ni][j] = 0.0f;

        load_stage(0, 0);
        load_stage(1, 1);
        __syncthreads();   // zero-STS of initial stages visible

#pragma unroll 1
        for (int it = 0; it < NIT; ++it) {
            const int ib = it & 1;
            mbar_wait(sb + ib * 16, ph[ib]);
            ph[ib] ^= 1;
            const uint32_t st = sb + TILES_OFF + ib * STAGE_B;
#pragma unroll
            for (int ks = 0; ks < 6; ++ks) {
                const uint32_t kb = (uint32_t)(ks * 32);
                uint32_t a[2][4], bf[4][4];
#pragma unroll
                for (int mi = 0; mi < 2; ++mi)
                    ldm4(a[mi], st + aOff[mi] + kb);
#pragma unroll
                for (int nj = 0; nj < 4; ++nj)
                    ldm4(bf[nj], st + bOff[nj] + kb);
#pragma unroll
                for (int nj = 0; nj < 4; ++nj)
#pragma unroll
                    for (int s2 = 0; s2 < 2; ++s2) {
                        const int ni = nj * 2 + s2;
                        const uint32_t b0 = bf[nj][s2 * 2];
                        const uint32_t b1 = bf[nj][s2 * 2 + 1];
#pragma unroll
                        for (int mi = 0; mi < 2; ++mi)
                            mma_fp16(acc[mi][ni], a[mi], b0, b1);
                    }
            }
            __syncthreads();                      // stage drained by all warps
            if (it + NSTAGE < NIT) load_stage(ib, it + NSTAGE);
        }

        // ---- epilogue for this tile ----
        float* ob = out + (size_t)b * COUT_ * NPIX_;
#pragma unroll
        for (int mi = 0; mi < 2; ++mi) {
            const int cout0 = m0 + mw + mi * 16 + lg;
#pragma unroll
            for (int ni = 0; ni < 8; ++ni) {
                const int nc = pix0 + nw + ni * 8 + lc * 2;
                float2* p0 = (float2*)(ob + (size_t)cout0 * NPIX_ + nc);
                float2* p1 = (float2*)(ob + (size_t)(cout0 + 8) * NPIX_ + nc);
                *p0 = make_float2(acc[mi][ni][0], acc[mi][ni][1]);
                *p1 = make_float2(acc[mi][ni][2], acc[mi][ni][3]);
            }
        }
    }
}

// ---------------------------------------------------------------------------
extern "C" void kernel_launch(void* const* d_in, const int* in_sizes, int n_in,
                              void* d_out, int out_size) {
    const float* x = (const float*)d_in[0];   // [32,256,64,64]
    const float* w = (const float*)d_in[1];   // [256,256,3,3]
    float* out = (float*)d_out;               // [32,256,32,32]

    cudaFuncSetAttribute(conv_fp16_kernel,
                         cudaFuncAttributeMaxDynamicSharedMemorySize, SMEM_TOTAL);

    transform_kernel<<<2304 + 32768, 256>>>(x, w);
    conv_fp16_kernel<<<NCTA, 256, SMEM_TOTAL>>>(out);
}

// round 15
// speedup vs baseline: 1.0213x; 1.0213x over previous
#include <cuda_runtime.h>
#include <cuda_fp16.h>
#include <cstdint>

// ---------------------------------------------------------------------------
// B=32, CIN=256, COUT=256, 64x64 -> 32x32, 3x3 stride2 pad1 conv. Crop mask
// all-True => plain conv. Single-pass fp16 m16n8k16 implicit GEMM.
// Round 15: R13 base (KC=96, 2-stage, paired iters, 2 CTAs/SM) +
// B-fragment double-buffering across ks (de-phase LDSM vs MMA) +
// vectorized (16B) prologue stores.
// ---------------------------------------------------------------------------

#define B_    32
#define CIN_  256
#define COUT_ 256
#define H_    64
#define W_    64
#define HW_   4096
#define NPIX_ 1024
#define KTOT  2304

#define BM 128
#define BN 128
#define KC 96
#define NIT 24                 // 2304 / 96

#define ROW_B    208           // 192B payload + 16B pad
#define A_OFF    0
#define B_OFF2   (128 * ROW_B)             // 26624
#define STAGE_B  (B_OFF2 + 128 * ROW_B)    // 53248
#define TILES_OFF 1024
#define NSTAGE   2
#define SMEM_TOTAL (TILES_OFF + NSTAGE * STAGE_B)   // 107520 (x2 CTAs = 215040)

__device__ __align__(128) __half g_A[COUT_ * KTOT];             // [cout][p*256+cin]
__device__ __align__(128) __half g_X[(size_t)B_ * HW_ * CIN_];  // [b][s][cin]

// ---------------------------------------------------------------------------
__device__ __forceinline__ uint32_t smem_u32(const void* p) {
    uint32_t a;
    asm("{ .reg .u64 t; cvta.to.shared.u64 t, %1; cvt.u32.u64 %0, t; }" : "=r"(a) : "l"(p));
    return a;
}
__device__ __forceinline__ void bulk_g2s(uint32_t dst, const void* src, uint32_t bytes,
                                         uint32_t mbar) {
    asm volatile(
        "cp.async.bulk.shared::cluster.global.mbarrier::complete_tx::bytes "
        "[%0], [%1], %2, [%3];"
        :: "r"(dst), "l"(src), "r"(bytes), "r"(mbar) : "memory");
}
__device__ __forceinline__ void mbar_init(uint32_t a, uint32_t cnt) {
    asm volatile("mbarrier.init.shared.b64 [%0], %1;" :: "r"(a), "r"(cnt) : "memory");
}
__device__ __forceinline__ void mbar_expect_tx(uint32_t a, uint32_t tx) {
    asm volatile("mbarrier.arrive.expect_tx.shared.b64 _, [%0], %1;"
                 :: "r"(a), "r"(tx) : "memory");
}
__device__ __forceinline__ void mbar_wait(uint32_t a, uint32_t parity) {
    asm volatile(
        "{\n\t.reg .pred P1;\n\t"
        "W_%=:\n\t"
        "mbarrier.try_wait.parity.acquire.cta.shared::cta.b64 P1, [%0], %1, 0x989680;\n\t"
        "@!P1 bra W_%=;\n\t}"
        :: "r"(a), "r"(parity) : "memory");
}
__device__ __forceinline__ void mma_fp16(float* d, const uint32_t* a, uint32_t b0, uint32_t b1) {
    asm volatile(
        "mma.sync.aligned.m16n8k16.row.col.f32.f16.f16.f32 "
        "{%0,%1,%2,%3}, {%4,%5,%6,%7}, {%8,%9}, {%0,%1,%2,%3};"
        : "+f"(d[0]), "+f"(d[1]), "+f"(d[2]), "+f"(d[3])
        : "r"(a[0]), "r"(a[1]), "r"(a[2]), "r"(a[3]), "r"(b0), "r"(b1));
}
__device__ __forceinline__ void ldm4(uint32_t* r, uint32_t addr) {
    asm volatile("ldmatrix.sync.aligned.m8n8.x4.shared.b16 {%0,%1,%2,%3}, [%4];"
                 : "=r"(r[0]), "=r"(r[1]), "=r"(r[2]), "=r"(r[3]) : "r"(addr));
}

// ---------------------------------------------------------------------------
// Fused prologue: blocks [0, 2304) -> weight convert; rest -> x convert
// ---------------------------------------------------------------------------
__global__ void transform_kernel(const float* __restrict__ x, const float* __restrict__ w) {
    __shared__ float tile[32][33];   // tile[c_local][s_local]
    const int tid = threadIdx.x;
    if (blockIdx.x < 2304) {
        int idx = blockIdx.x * 256 + tid;   // linear over [cout][p][cin]
        int cin = idx & 255;
        int p = (idx >> 8) % 9;
        int cout = idx / KTOT;
        g_A[idx] = __float2half_rn(w[cout * KTOT + cin * 9 + p]);
        return;
    }
    const int t = blockIdx.x - 2304;
    const int s0 = (t & 127) * 32;
    const int c0 = ((t >> 7) & 7) * 32;
    const int b = t >> 10;
    const int tx = tid & 31, ty = tid >> 5;         // 32 x 8
    const float* xb = x + ((size_t)b * CIN_ + c0) * HW_ + s0;
#pragma unroll
    for (int k = 0; k < 4; ++k)
        tile[ty + 8 * k][tx] = xb[(size_t)(ty + 8 * k) * HW_ + tx];   // tile[c][s]
    __syncthreads();
    // 16B vectorized stores: threads 0..127, each writes 8 channels at one s
    if (tid < 128) {
        const int s = tid >> 2;
        const int c = (tid & 3) * 8;
        __half2 h0 = __floats2half2_rn(tile[c + 0][s], tile[c + 1][s]);
        __half2 h1 = __floats2half2_rn(tile[c + 2][s], tile[c + 3][s]);
        __half2 h2 = __floats2half2_rn(tile[c + 4][s], tile[c + 5][s]);
        __half2 h3 = __floats2half2_rn(tile[c + 6][s], tile[c + 7][s]);
        uint4 v;
        v.x = *(uint32_t*)&h0; v.y = *(uint32_t*)&h1;
        v.z = *(uint32_t*)&h2; v.w = *(uint32_t*)&h3;
        size_t o = ((size_t)b * HW_ + s0 + s) * CIN_ + c0 + c;
        *(uint4*)(g_X + o) = v;
    }
}

// ---------------------------------------------------------------------------
// Main fp16 implicit-GEMM. grid (2, 256), 256 threads (8 warps), 2 CTAs/SM.
// ---------------------------------------------------------------------------
__global__ void __launch_bounds__(256, 2) conv_fp16_kernel(float* __restrict__ out) {
    extern __shared__ char smem[];
    const uint32_t sb = smem_u32(smem);
    const int tid = threadIdx.x;
    const int lane = tid & 31, warp = tid >> 5;
    const int m0 = blockIdx.x * BM;
    const int n0 = blockIdx.y * BN;
    const int b = n0 >> 10;
    const int pix0 = n0 & (NPIX_ - 1);

    if (tid < NSTAGE) mbar_init(sb + tid * 16, 1);
    asm volatile("fence.proxy.async.shared::cta;" ::: "memory");
    __syncthreads();

    const int pixL = pix0 + (tid & 127);
    const int ohL = pixL >> 5, owL = pixL & 31;
    const __half* gX0 = g_X + (size_t)b * HW_ * CIN_;

    auto inv_rows = [&](int p) -> int {
        const int kh = p / 3, kw = p - (p / 3) * 3;
        int inv = (kw == 0 ? 4 : 0) + ((kh == 0 && pix0 == 0) ? 32 : 0);
        if (kw == 0 && kh == 0 && pix0 == 0) inv -= 1;
        return inv;
    };

    auto load_stage = [&](int buf, int it) {
        const int k0 = it * KC;
        const int p1 = k0 >> 8;
        const int o1 = k0 & 255;
        const int len1 = (256 - o1 < KC) ? (256 - o1) : KC;
        const int len2 = KC - len1;
        const uint32_t st = sb + TILES_OFF + buf * STAGE_B;
        const uint32_t mb = sb + buf * 16;
        if (tid == 0) {
            uint32_t txB = 2u * (uint32_t)len1 * (uint32_t)(128 - inv_rows(p1));
            if (len2) txB += 2u * (uint32_t)len2 * (uint32_t)(128 - inv_rows(p1 + 1));
            mbar_expect_tx(mb, 128u * 192u + txB);
        }
        const int r = tid & 127;
        if (tid < 128) {
            bulk_g2s(st + A_OFF + r * ROW_B,
                     g_A + (size_t)(m0 + r) * KTOT + k0, KC * 2, mb);
        } else {
            const uint32_t dst = st + B_OFF2 + r * ROW_B;
            {
                const int kh = p1 / 3, kw = p1 - (p1 / 3) * 3;
                const int ih = ohL * 2 - 1 + kh;
                const int iw = owL * 2 - 1 + kw;
                if (((unsigned)ih < (unsigned)H_) && ((unsigned)iw < (unsigned)W_)) {
                    bulk_g2s(dst, gX0 + (size_t)(ih * W_ + iw) * CIN_ + o1, len1 * 2, mb);
                } else {
                    for (int j = 0; j < len1 * 2; j += 16)
                        asm volatile("st.shared.v4.b32 [%0], {%1, %1, %1, %1};"
                                     :: "r"(dst + j), "r"(0u) : "memory");
                }
            }
            if (len2) {
                const int p2 = p1 + 1;
                const int kh = p2 / 3, kw = p2 - (p2 / 3) * 3;
                const int ih = ohL * 2 - 1 + kh;
                const int iw = owL * 2 - 1 + kw;
                const uint32_t d2 = dst + len1 * 2;
                if (((unsigned)ih < (unsigned)H_) && ((unsigned)iw < (unsigned)W_)) {
                    bulk_g2s(d2, gX0 + (size_t)(ih * W_ + iw) * CIN_, len2 * 2, mb);
                } else {
                    for (int j = 0; j < len2 * 2; j += 16)
                        asm volatile("st.shared.v4.b32 [%0], {%1, %1, %1, %1};"
                                     :: "r"(d2 + j), "r"(0u) : "memory");
                }
            }
        }
    };

    float acc[2][8][4];
#pragma unroll
    for (int mi = 0; mi < 2; ++mi)
#pragma unroll
        for (int ni = 0; ni < 8; ++ni)
#pragma unroll
            for (int j = 0; j < 4; ++j) acc[mi][ni][j] = 0.0f;

    load_stage(0, 0);
    load_stage(1, 1);
    __syncthreads();   // zero-STS of initial stages visible

    const int mw = (warp >> 1) * 32;      // 0,32,64,96
    const int nw = (warp & 1) * 64;       // 0,64
    uint32_t aOff[2], bOff[4];
#pragma unroll
    for (int mi = 0; mi < 2; ++mi)
        aOff[mi] = (uint32_t)(A_OFF + (mw + mi * 16 + (lane & 15)) * ROW_B
                   + (lane >> 4) * 16);
#pragma unroll
    for (int nj = 0; nj < 4; ++nj)
        bOff[nj] = (uint32_t)(B_OFF2
                 + (nw + nj * 16 + (lane & 7) + (lane >> 4) * 8) * ROW_B
                 + ((lane >> 3) & 1) * 16);

    int ph = 0;

    // compute one stage with B-fragment double-buffering across ks
    auto compute_stage = [&](int buf) {
        const uint32_t st = sb + TILES_OFF + buf * STAGE_B;
        uint32_t bf[2][4][4];
#pragma unroll
        for (int nj = 0; nj < 4; ++nj)
            ldm4(bf[0][nj], st + bOff[nj]);
#pragma unroll
        for (int ks = 0; ks < 6; ++ks) {
            const int cur = ks & 1;
            uint32_t a[2][4];
#pragma unroll
            for (int mi = 0; mi < 2; ++mi)
                ldm4(a[mi], st + aOff[mi] + (uint32_t)(ks * 32));
            if (ks < 5) {
#pragma unroll
                for (int nj = 0; nj < 4; ++nj)
                    ldm4(bf[cur ^ 1][nj], st + bOff[nj] + (uint32_t)((ks + 1) * 32));
            }
#pragma unroll
            for (int nj = 0; nj < 4; ++nj)
#pragma unroll
                for (int s2 = 0; s2 < 2; ++s2) {
                    const int ni = nj * 2 + s2;
                    const uint32_t b0 = bf[cur][nj][s2 * 2];
                    const uint32_t b1 = bf[cur][nj][s2 * 2 + 1];
#pragma unroll
                    for (int mi = 0; mi < 2; ++mi)
                        mma_fp16(acc[mi][ni], a[mi], b0, b1);
                }
        }
    };

#pragma unroll 1
    for (int jp = 0; jp < NIT / 2; ++jp) {
        mbar_wait(sb + 0 * 16, ph);
        compute_stage(0);
        mbar_wait(sb + 1 * 16, ph);
        compute_stage(1);
        ph ^= 1;
        __syncthreads();                      // both stages drained by all warps
        if (2 * jp + 2 < NIT) {
            load_stage(0, 2 * jp + 2);
            load_stage(1, 2 * jp + 3);
        }
    }

    // ---- epilogue ----
    const int lg = lane >> 2;
    const int lc = lane & 3;
    float* ob = out + (size_t)b * COUT_ * NPIX_;
#pragma unroll
    for (int mi = 0; mi < 2; ++mi) {
        const int cout0 = m0 + mw + mi * 16 + lg;
#pragma unroll
        for (int ni = 0; ni < 8; ++ni) {
            const int nc = pix0 + nw + ni * 8 + lc * 2;
            float2* p0 = (float2*)(ob + (size_t)cout0 * NPIX_ + nc);
            float2* p1 = (float2*)(ob + (size_t)(cout0 + 8) * NPIX_ + nc);
            *p0 = make_float2(acc[mi][ni][0], acc[mi][ni][1]);
            *p1 = make_float2(acc[mi][ni][2], acc[mi][ni][3]);
        }
    }
}

// ---------------------------------------------------------------------------
extern "C" void kernel_launch(void* const* d_in, const int* in_sizes, int n_in,
                              void* d_out, int out_size) {
    const float* x = (const float*)d_in[0];   // [32,256,64,64]
    const float* w = (const float*)d_in[1];   // [256,256,3,3]
    float* out = (float*)d_out;               // [32,256,32,32]

    cudaFuncSetAttribute(conv_fp16_kernel,
                         cudaFuncAttributeMaxDynamicSharedMemorySize, SMEM_TOTAL);

    transform_kernel<<<2304 + 32768, 256>>>(x, w);
    {
        dim3 grid(COUT_ / BM, (B_ * NPIX_) / BN);   // (2, 256)
        conv_fp16_kernel<<<grid, 256, SMEM_TOTAL>>>(out);
    }
}